// round 4
// baseline (speedup 1.0000x reference)
#include <cuda_runtime.h>
#include <cuda_fp16.h>

#define R_TOT   16384      // H*W rays
#define KPRIM   32
#define NSTEPS  64
#define DTSTEP  (1.0f/64.0f)

// Packed template: per (k,z,y,x): {half2 r(x,x+1), g(x,x+1), b(x,x+1), a(x,x+1)} = 16B
__device__ uint4 g_tpair[KPRIM * 4096];   // 2 MB, L2-resident

// --- Prologue: pack template [K,4,16,16,16] fp32 -> fp16 corner pairs ---
__global__ void pack_tmpl_kernel(const float* __restrict__ tmpl) {
    int idx = blockIdx.x * blockDim.x + threadIdx.x;
    if (idx >= KPRIM * 4096) return;
    int k = idx >> 12;
    int v = idx & 4095;            // z*256 + y*16 + x
    int x = v & 15;
    int x1 = (x < 15) ? 1 : 0;     // clamp x+1
    const float* b = tmpl + (size_t)k * 4 * 4096;
    __half2 hr = __floats2half2_rn(b[v],           b[v + x1]);
    __half2 hg = __floats2half2_rn(b[4096 + v],    b[4096 + v + x1]);
    __half2 hb = __floats2half2_rn(b[8192 + v],    b[8192 + v + x1]);
    __half2 ha = __floats2half2_rn(b[12288 + v],   b[12288 + v + x1]);
    uint4 q;
    q.x = *(unsigned int*)&hr;
    q.y = *(unsigned int*)&hg;
    q.z = *(unsigned int*)&hb;
    q.w = *(unsigned int*)&ha;
    g_tpair[idx] = q;
}

__device__ __forceinline__ float4 xlerp4(uint4 q, float fx) {
    float2 r = __half22float2(*(__half2*)&q.x);
    float2 g = __half22float2(*(__half2*)&q.y);
    float2 b = __half22float2(*(__half2*)&q.z);
    float2 a = __half22float2(*(__half2*)&q.w);
    return make_float4(fmaf(fx, r.y - r.x, r.x),
                       fmaf(fx, g.y - g.x, g.x),
                       fmaf(fx, b.y - b.x, b.x),
                       fmaf(fx, a.y - a.x, a.x));
}

// --- Main march: one warp per ray, one lane per primitive, 2-stage pipeline ---
__global__ void __launch_bounds__(256) march_kernel(
    const float* __restrict__ raypos,
    const float* __restrict__ raydir,
    const float* __restrict__ tminmax,
    const float* __restrict__ primpos,
    const float* __restrict__ primrot,
    const float* __restrict__ primscale,
    float* __restrict__ out)
{
    int gtid = blockIdx.x * blockDim.x + threadIdx.x;
    int ray  = gtid >> 5;
    int lane = threadIdx.x & 31;
    if (ray >= R_TOT) return;

    // Per-lane primitive parameters (registers)
    float ppx = primpos[lane * 3 + 0];
    float ppy = primpos[lane * 3 + 1];
    float ppz = primpos[lane * 3 + 2];
    float r00 = primrot[lane * 9 + 0], r01 = primrot[lane * 9 + 1], r02 = primrot[lane * 9 + 2];
    float r10 = primrot[lane * 9 + 3], r11 = primrot[lane * 9 + 4], r12 = primrot[lane * 9 + 5];
    float r20 = primrot[lane * 9 + 6], r21 = primrot[lane * 9 + 7], r22 = primrot[lane * 9 + 8];
    float s0 = primscale[lane * 3 + 0];
    float s1 = primscale[lane * 3 + 1];
    float s2 = primscale[lane * 3 + 2];

    float rpx = raypos[ray * 3 + 0];
    float rpy = raypos[ray * 3 + 1];
    float rpz = raypos[ray * 3 + 2];
    float rdx = raydir[ray * 3 + 0];
    float rdy = raydir[ray * 3 + 1];
    float rdz = raydir[ray * 3 + 2];
    float tmin = tminmax[ray * 2 + 0];
    float tmax = tminmax[ray * 2 + 1];

    const uint4* __restrict__ T = g_tpair + lane * 4096;

    // Steps with t = tmin + i*DT < tmax  (exact: i/64 and tmax*64 are exact fp32)
    int nsteps = (int)ceilf((tmax - tmin) * 64.0f);
    nsteps = min(nsteps, NSTEPS);

    float rgbx = 0.f, rgby = 0.f, rgbz = 0.f, alpha = 0.f;

    // ---- stage A for a given step: transform, index, issue loads ----
    #define STAGE_A(I, INS, FX, FY, FZ, Q00, Q01, Q10, Q11)                        \
    {                                                                              \
        float t  = fmaf((float)(I), DTSTEP, tmin);                                 \
        float px = fmaf(rdx, t, rpx);                                              \
        float py = fmaf(rdy, t, rpy);                                              \
        float pz = fmaf(rdz, t, rpz);                                              \
        float xlx = px - ppx, xly = py - ppy, xlz = pz - ppz;                      \
        float y0 = (r00 * xlx + r01 * xly + r02 * xlz) * s0;                       \
        float y1 = (r10 * xlx + r11 * xly + r12 * xlz) * s1;                       \
        float y2 = (r20 * xlx + r21 * xly + r22 * xlz) * s2;                       \
        INS = (fabsf(y0) <= 1.0f) & (fabsf(y1) <= 1.0f) & (fabsf(y2) <= 1.0f);     \
        float gz = (y0 + 1.0f) * 7.5f;                                             \
        float gy = (y1 + 1.0f) * 7.5f;                                             \
        float gx = (y2 + 1.0f) * 7.5f;                                             \
        int iz = min(max((int)floorf(gz), 0), 14);                                 \
        int iy = min(max((int)floorf(gy), 0), 14);                                 \
        int ix = min(max((int)floorf(gx), 0), 14);                                 \
        FZ = fminf(fmaxf(gz - (float)iz, 0.f), 1.f);                               \
        FY = fminf(fmaxf(gy - (float)iy, 0.f), 1.f);                               \
        FX = fminf(fmaxf(gx - (float)ix, 0.f), 1.f);                               \
        int base = iz * 256 + iy * 16 + ix;                                        \
        if (INS) {                                                                 \
            Q00 = __ldg(T + base);                                                 \
            Q01 = __ldg(T + base + 16);                                            \
            Q10 = __ldg(T + base + 256);                                           \
            Q11 = __ldg(T + base + 272);                                           \
        }                                                                          \
    }

    bool  insC;  float fxC, fyC, fzC;  uint4 q00C, q01C, q10C, q11C;
    bool  insN;  float fxN, fyN, fzN;  uint4 q00N, q01N, q10N, q11N;

    if (nsteps > 0) {
        STAGE_A(0, insC, fxC, fyC, fzC, q00C, q01C, q10C, q11C);
    }

    #pragma unroll 1
    for (int i = 0; i < nsteps; i++) {
        // ---- stage B(i): lerp current sample ----
        float sx = 0.f, sy = 0.f, sz = 0.f, sw = 0.f;
        if (insC) {
            float4 a00 = xlerp4(q00C, fxC);
            float4 a01 = xlerp4(q01C, fxC);
            float4 a10 = xlerp4(q10C, fxC);
            float4 a11 = xlerp4(q11C, fxC);
            float b0x = fmaf(fyC, a01.x - a00.x, a00.x);
            float b0y = fmaf(fyC, a01.y - a00.y, a00.y);
            float b0z = fmaf(fyC, a01.z - a00.z, a00.z);
            float b0w = fmaf(fyC, a01.w - a00.w, a00.w);
            float b1x = fmaf(fyC, a11.x - a10.x, a10.x);
            float b1y = fmaf(fyC, a11.y - a10.y, a10.y);
            float b1z = fmaf(fyC, a11.z - a10.z, a10.z);
            float b1w = fmaf(fyC, a11.w - a10.w, a10.w);
            sx = fmaf(fzC, b1x - b0x, b0x);
            sy = fmaf(fzC, b1y - b0y, b0y);
            sz = fmaf(fzC, b1z - b0z, b0z);
            sw = fmaf(fzC, b1w - b0w, b0w);
        }

        // ---- stage A(i+1): prefetch next sample (overlaps butterfly below) ----
        STAGE_A(i + 1, insN, fxN, fyN, fzN, q00N, q01N, q10N, q11N);

        // ---- warp-sum of alpha channel (5 dependent SHFLs) ----
        #pragma unroll
        for (int off = 16; off; off >>= 1)
            sw += __shfl_xor_sync(0xffffffffu, sw, off);

        // ---- composite (alpha >= 0 always; lower clamp dead) ----
        float na = fminf(fmaf(sw, DTSTEP, alpha), 1.0f);
        float contrib = na - alpha;         // warp-uniform
        rgbx = fmaf(sx, contrib, rgbx);
        rgby = fmaf(sy, contrib, rgby);
        rgbz = fmaf(sz, contrib, rgbz);
        alpha = na;
        if (alpha >= 1.0f) break;           // saturated: all later contribs 0

        insC = insN; fxC = fxN; fyC = fyN; fzC = fzN;
        q00C = q00N; q01C = q01N; q10C = q10N; q11C = q11N;
    }

    // Final rgb reduction across the warp
    #pragma unroll
    for (int off = 16; off; off >>= 1) {
        rgbx += __shfl_xor_sync(0xffffffffu, rgbx, off);
        rgby += __shfl_xor_sync(0xffffffffu, rgby, off);
        rgbz += __shfl_xor_sync(0xffffffffu, rgbz, off);
    }

    if (lane == 0) {
        // out layout: rayrgb [1,3,H,W] | rayalpha [1,1,H,W] | rayrgba [1,4,H,W]
        out[0 * R_TOT + ray] = rgbx;
        out[1 * R_TOT + ray] = rgby;
        out[2 * R_TOT + ray] = rgbz;
        out[3 * R_TOT + ray] = alpha;
        out[4 * R_TOT + ray] = rgbx;
        out[5 * R_TOT + ray] = rgby;
        out[6 * R_TOT + ray] = rgbz;
        out[7 * R_TOT + ray] = alpha;
    }
}

extern "C" void kernel_launch(void* const* d_in, const int* in_sizes, int n_in,
                              void* d_out, int out_size) {
    const float* raypos    = (const float*)d_in[0];
    const float* raydir    = (const float*)d_in[1];
    const float* tminmax   = (const float*)d_in[2];
    const float* primpos   = (const float*)d_in[3];
    const float* primrot   = (const float*)d_in[4];
    const float* primscale = (const float*)d_in[5];
    const float* tmpl      = (const float*)d_in[6];
    float* out = (float*)d_out;

    pack_tmpl_kernel<<<(KPRIM * 4096 + 255) / 256, 256>>>(tmpl);

    int threads = R_TOT * 32;
    march_kernel<<<threads / 256, 256>>>(raypos, raydir, tminmax,
                                         primpos, primrot, primscale, out);
}

// round 6
// speedup vs baseline: 1.2164x; 1.2164x over previous
#include <cuda_runtime.h>
#include <cuda_fp16.h>

#define R_TOT   16384      // H*W rays
#define KPRIM   32
#define NSTEPS  64
#define DTSTEP  (1.0f/64.0f)

// Packed template: per (k,z,y,x): {half2 r(x,x+1), g(x,x+1), b(x,x+1), a(x,x+1)} = 16B
__device__ uint4 g_tpair[KPRIM * 4096];   // 2 MB, L2-resident

// --- Prologue: pack template [K,4,16,16,16] fp32 -> fp16 corner pairs ---
__global__ void pack_tmpl_kernel(const float* __restrict__ tmpl) {
    int idx = blockIdx.x * blockDim.x + threadIdx.x;
    if (idx >= KPRIM * 4096) return;
    int k = idx >> 12;
    int v = idx & 4095;            // z*256 + y*16 + x
    int x = v & 15;
    int x1 = (x < 15) ? 1 : 0;     // clamp x+1
    const float* b = tmpl + (size_t)k * 4 * 4096;
    __half2 hr = __floats2half2_rn(b[v],           b[v + x1]);
    __half2 hg = __floats2half2_rn(b[4096 + v],    b[4096 + v + x1]);
    __half2 hb = __floats2half2_rn(b[8192 + v],    b[8192 + v + x1]);
    __half2 ha = __floats2half2_rn(b[12288 + v],   b[12288 + v + x1]);
    uint4 q;
    q.x = *(unsigned int*)&hr;
    q.y = *(unsigned int*)&hg;
    q.z = *(unsigned int*)&hb;
    q.w = *(unsigned int*)&ha;
    g_tpair[idx] = q;
}

__device__ __forceinline__ float4 xlerp4(uint4 q, float fx) {
    float2 r = __half22float2(*(__half2*)&q.x);
    float2 g = __half22float2(*(__half2*)&q.y);
    float2 b = __half22float2(*(__half2*)&q.z);
    float2 a = __half22float2(*(__half2*)&q.w);
    return make_float4(fmaf(fx, r.y - r.x, r.x),
                       fmaf(fx, g.y - g.x, g.x),
                       fmaf(fx, b.y - b.x, b.x),
                       fmaf(fx, a.y - a.x, a.x));
}

// --- Main march: one warp per ray, one lane per primitive, affine-in-t transform ---
__global__ void __launch_bounds__(256) march_kernel(
    const float* __restrict__ raypos,
    const float* __restrict__ raydir,
    const float* __restrict__ tminmax,
    const float* __restrict__ primpos,
    const float* __restrict__ primrot,
    const float* __restrict__ primscale,
    float* __restrict__ out)
{
    int gtid = blockIdx.x * blockDim.x + threadIdx.x;
    int ray  = gtid >> 5;
    int lane = threadIdx.x & 31;
    if (ray >= R_TOT) return;

    float rpx = raypos[ray * 3 + 0];
    float rpy = raypos[ray * 3 + 1];
    float rpz = raypos[ray * 3 + 2];
    float rdx = raydir[ray * 3 + 0];
    float rdy = raydir[ray * 3 + 1];
    float rdz = raydir[ray * 3 + 2];
    float tmin = tminmax[ray * 2 + 0];
    float tmax = tminmax[ray * 2 + 1];

    // Affine transform coefficients: y_c(t) = a_c + t * b_c  (per-lane prim)
    float a0, a1, a2, b0, b1, b2;
    {
        float ppx = primpos[lane * 3 + 0];
        float ppy = primpos[lane * 3 + 1];
        float ppz = primpos[lane * 3 + 2];
        float r00 = primrot[lane * 9 + 0], r01 = primrot[lane * 9 + 1], r02 = primrot[lane * 9 + 2];
        float r10 = primrot[lane * 9 + 3], r11 = primrot[lane * 9 + 4], r12 = primrot[lane * 9 + 5];
        float r20 = primrot[lane * 9 + 6], r21 = primrot[lane * 9 + 7], r22 = primrot[lane * 9 + 8];
        float s0 = primscale[lane * 3 + 0];
        float s1 = primscale[lane * 3 + 1];
        float s2 = primscale[lane * 3 + 2];
        float dx = rpx - ppx, dy = rpy - ppy, dz = rpz - ppz;
        a0 = (r00 * dx + r01 * dy + r02 * dz) * s0;
        a1 = (r10 * dx + r11 * dy + r12 * dz) * s1;
        a2 = (r20 * dx + r21 * dy + r22 * dz) * s2;
        b0 = (r00 * rdx + r01 * rdy + r02 * rdz) * s0;
        b1 = (r10 * rdx + r11 * rdy + r12 * rdz) * s1;
        b2 = (r20 * rdx + r21 * rdy + r22 * rdz) * s2;
    }

    // Steps with t = tmin + i*DT < tmax
    int nsteps = (int)ceilf((tmax - tmin) * 64.0f);
    nsteps = min(nsteps, NSTEPS);

    // Per-lane slab interval [te, tx]: |a_c + t b_c| <= 1 for all c
    float te = -1e30f, tx = 1e30f;
    bool nonempty = true;
    {
        #define SLAB(A, B)                                                   \
        {                                                                    \
            if ((B) != 0.0f) {                                               \
                float u = (-1.0f - (A)) / (B);                               \
                float v = ( 1.0f - (A)) / (B);                               \
                te = fmaxf(te, fminf(u, v));                                 \
                tx = fminf(tx, fmaxf(u, v));                                 \
            } else if (fabsf(A) > 1.0f) {                                    \
                nonempty = false;                                            \
            }                                                                \
        }
        SLAB(a0, b0) SLAB(a1, b1) SLAB(a2, b2)
        #undef SLAB
        if (te > tx) nonempty = false;
    }

    // Step-index bounds (widened 1 step for rounding safety)
    int ie, ix;
    if (nonempty) {
        float fe = fminf(fmaxf((te - tmin) * 64.0f, -2.0f), 100.0f);
        float fx_ = fminf(fmaxf((tx - tmin) * 64.0f, -2.0f), 100.0f);
        ie = (int)floorf(fe) - 1;
        ix = (int)ceilf(fx_) + 1;
    } else {
        ie = 1 << 30;
        ix = -1;
    }
    int istart, iend;
    asm("redux.sync.min.s32 %0, %1, 0xffffffff;" : "=r"(istart) : "r"(ie));
    asm("redux.sync.max.s32 %0, %1, 0xffffffff;" : "=r"(iend)   : "r"(ix));
    istart = max(istart, 0);
    iend   = min(iend, nsteps - 1);

    float rgbx = 0.f, rgby = 0.f, rgbz = 0.f, alpha = 0.f;

    #pragma unroll 1
    for (int i = istart; i <= iend; i++) {
        float t  = fmaf((float)i, DTSTEP, tmin);
        float y0 = fmaf(t, b0, a0);
        float y1 = fmaf(t, b1, a1);
        float y2 = fmaf(t, b2, a2);

        float sx = 0.f, sy = 0.f, sz = 0.f, sw = 0.f;
        if (fabsf(y0) <= 1.0f && fabsf(y1) <= 1.0f && fabsf(y2) <= 1.0f) {
            // component 0 -> z index, 1 -> y, 2 -> x ; g in [0,15] when inside
            float gz = (y0 + 1.0f) * 7.5f;
            float gy = (y1 + 1.0f) * 7.5f;
            float gx = (y2 + 1.0f) * 7.5f;
            int iz = min((int)gz, 14);
            int iy = min((int)gy, 14);
            int ixx = min((int)gx, 14);
            float fz = gz - (float)iz;
            float fy = gy - (float)iy;
            float fx = gx - (float)ixx;

            const uint4* __restrict__ T = g_tpair + (lane << 12);
            int base = iz * 256 + iy * 16 + ixx;
            uint4 q00 = __ldg(T + base);            // (iz,  iy)
            uint4 q01 = __ldg(T + base + 16);       // (iz,  iy+1)
            uint4 q10 = __ldg(T + base + 256);      // (iz+1,iy)
            uint4 q11 = __ldg(T + base + 272);      // (iz+1,iy+1)

            float4 c00 = xlerp4(q00, fx);
            float4 c01 = xlerp4(q01, fx);
            float4 c10 = xlerp4(q10, fx);
            float4 c11 = xlerp4(q11, fx);

            float d0x = fmaf(fy, c01.x - c00.x, c00.x);
            float d0y = fmaf(fy, c01.y - c00.y, c00.y);
            float d0z = fmaf(fy, c01.z - c00.z, c00.z);
            float d0w = fmaf(fy, c01.w - c00.w, c00.w);
            float d1x = fmaf(fy, c11.x - c10.x, c10.x);
            float d1y = fmaf(fy, c11.y - c10.y, c10.y);
            float d1z = fmaf(fy, c11.z - c10.z, c10.z);
            float d1w = fmaf(fy, c11.w - c10.w, c10.w);

            sx = fmaf(fz, d1x - d0x, d0x);
            sy = fmaf(fz, d1y - d0y, d0y);
            sz = fmaf(fz, d1z - d0z, d0z);
            sw = fmaf(fz, d1w - d0w, d0w);
        }

        // Warp-sum of alpha channel (butterfly; fp32 REDUX not on sm_103)
        #pragma unroll
        for (int off = 16; off; off >>= 1)
            sw += __shfl_xor_sync(0xffffffffu, sw, off);

        float na = fminf(fmaf(sw, DTSTEP, alpha), 1.0f);
        float contrib = na - alpha;         // warp-uniform
        rgbx = fmaf(sx, contrib, rgbx);     // per-lane partial; reduced at the end
        rgby = fmaf(sy, contrib, rgby);
        rgbz = fmaf(sz, contrib, rgbz);
        alpha = na;
        if (alpha >= 1.0f) break;           // saturated: all later contribs 0
    }

    // Final rgb reduction across the warp
    #pragma unroll
    for (int off = 16; off; off >>= 1) {
        rgbx += __shfl_xor_sync(0xffffffffu, rgbx, off);
        rgby += __shfl_xor_sync(0xffffffffu, rgby, off);
        rgbz += __shfl_xor_sync(0xffffffffu, rgbz, off);
    }

    if (lane == 0) {
        // out layout: rayrgb [1,3,H,W] | rayalpha [1,1,H,W] | rayrgba [1,4,H,W]
        out[0 * R_TOT + ray] = rgbx;
        out[1 * R_TOT + ray] = rgby;
        out[2 * R_TOT + ray] = rgbz;
        out[3 * R_TOT + ray] = alpha;
        out[4 * R_TOT + ray] = rgbx;
        out[5 * R_TOT + ray] = rgby;
        out[6 * R_TOT + ray] = rgbz;
        out[7 * R_TOT + ray] = alpha;
    }
}

extern "C" void kernel_launch(void* const* d_in, const int* in_sizes, int n_in,
                              void* d_out, int out_size) {
    const float* raypos    = (const float*)d_in[0];
    const float* raydir    = (const float*)d_in[1];
    const float* tminmax   = (const float*)d_in[2];
    const float* primpos   = (const float*)d_in[3];
    const float* primrot   = (const float*)d_in[4];
    const float* primscale = (const float*)d_in[5];
    const float* tmpl      = (const float*)d_in[6];
    float* out = (float*)d_out;

    pack_tmpl_kernel<<<(KPRIM * 4096 + 255) / 256, 256>>>(tmpl);

    int threads = R_TOT * 32;
    march_kernel<<<threads / 256, 256>>>(raypos, raydir, tminmax,
                                         primpos, primrot, primscale, out);
}